// round 5
// baseline (speedup 1.0000x reference)
#include <cuda_runtime.h>

#define BDIM 8
#define NPTS 4096
#define DDIM 64
#define KNN 16
#define QPB 64                           // queries per phase-1 block
#define STRIPS 4
#define P1T (QPB * STRIPS)               // 256 threads
#define TILE 1024                        // candidates per smem tile
#define NT (NPTS / TILE)                 // 4 tiles
#define SUB (TILE / STRIPS)              // 256 candidates per strip per tile
#define DEPTH 12                         // smem buffer slots per thread
#define SEED 128

typedef unsigned long long ull;

__device__ int g_knn[BDIM * NPTS * KNN];   // 2 MB knn indices

// key = (sortable_bits(d) << 32) | idx. Monotone float->uint transform ->
// unsigned compare == exact lexicographic (d, idx) == jnp stable argsort.
__device__ __forceinline__ ull packK(float d, int m) {
    unsigned ub = __float_as_uint(d);
    ub ^= ((unsigned)((int)ub >> 31)) | 0x80000000u;
    return ((ull)ub << 32) | (unsigned)m;
}
__device__ __forceinline__ float thrOf(ull k) {
    unsigned h = (unsigned)(k >> 32);
    unsigned bits = (h & 0x80000000u) ? (h ^ 0x80000000u) : ~h;
    return __uint_as_float(bits);
}

__device__ __forceinline__ void insertK(ull (&key)[KNN], ull ck) {
#pragma unroll
    for (int j = 0; j < KNN; j++) {
        bool lt = ck < key[j];
        ull o = key[j];
        key[j] = lt ? ck : o;
        ck     = lt ? o  : ck;
    }
}

__device__ __forceinline__ float pdist(float4 q, float4 c) {
    float t = q.x * c.x;
    t = fmaf(q.y, c.y, t);
    t = fmaf(q.z, c.z, t);
    return fmaf(-2.0f, t, q.w + c.w);   // identical fp order to passing rounds
}

// ---------------- Phase 1: fused distance + exact top-16 --------------------
// 512 blocks x 256 threads = 64 queries x 4 strips. Candidates streamed in
// 1024-pt smem tiles; accepts buffered in SMEM [DEPTH][P1T], drained
// convergently with warp-max trips every 64-128 candidates.
#define KNN_SMEM (TILE*16 + TILE*12 + DEPTH*P1T*8)   // 16K + 12K + 24K = 52KB

extern "C" __global__ void __launch_bounds__(P1T)
knn_kernel(const float* __restrict__ xyz)
{
    extern __shared__ char smem_raw[];
    float4* cand = (float4*)smem_raw;                          // [TILE]
    float*  raw  = (float*)(smem_raw + TILE * 16);             // [TILE*3]
    ull*    buf  = (ull*)(smem_raw + TILE * 16 + TILE * 12);   // [DEPTH][P1T]

    int b  = blockIdx.x >> 6;            // 64 blocks per batch
    int n0 = (blockIdx.x & 63) * QPB;
    const float* xb = xyz + (size_t)b * NPTS * 3;

    int lq = threadIdx.x & (QPB - 1);
    int s  = threadIdx.x >> 6;           // strip 0..3 (warp-uniform)
    int n  = n0 + lq;

    float qx = xb[3*n], qy = xb[3*n+1], qz = xb[3*n+2];
    float qw = qx*qx; qw = fmaf(qy, qy, qw); qw = fmaf(qz, qz, qw);
    float4 q = make_float4(qx, qy, qz, qw);

    ull key[KNN];
#pragma unroll
    for (int j = 0; j < KNN; j++) key[j] = ~0ull;

#pragma unroll 1
    for (int t = 0; t < NT; t++) {
        int p0 = t * TILE;
        __syncthreads();                 // previous tile fully consumed
        for (int i = threadIdx.x; i < TILE * 3; i += P1T)
            raw[i] = xb[p0 * 3 + i];
        __syncthreads();
        for (int p = threadIdx.x; p < TILE; p += P1T) {
            float cx = raw[3*p], cy = raw[3*p+1], cz = raw[3*p+2];
            float cw = cx*cx; cw = fmaf(cy, cy, cw); cw = fmaf(cz, cz, cw);
            cand[p] = make_float4(cx, cy, cz, cw);
        }
        __syncthreads();

        int c0 = s * SUB;                // this strip's slice of the tile
        int m0 = p0 + c0;
        int start = 0;

        if (t == 0) {                    // seed: guarded direct inserts
#pragma unroll 1
            for (int i = 0; i < SEED; i++) {
                ull ck = packK(pdist(q, cand[c0 + i]), m0 + i);
                if (ck < key[KNN - 1]) insertK(key, ck);
            }
            start = SEED;
        }

        int csz = (t == 0) ? 64 : 128;   // chunk size (block-uniform)
#pragma unroll 1
        for (int i0 = start; i0 < SUB; i0 += csz) {
            float thr = thrOf(key[KNN - 1]);
            int cnt = 0;
#pragma unroll 4
            for (int i = i0; i < i0 + csz; i++) {
                float d = pdist(q, cand[c0 + i]);
                if (d <= thr) {          // <= keeps tie exactness
                    ull ck = packK(d, m0 + i);
                    if (cnt < DEPTH) { buf[cnt * P1T + threadIdx.x] = ck; cnt++; }
                    else              insertK(key, ck);   // rare overflow
                }
            }
            int cm = cnt;                // convergent warp-max trip count
#pragma unroll
            for (int o = 16; o > 0; o >>= 1) {
                int t2 = __shfl_xor_sync(0xffffffffu, cm, o);
                cm = cm > t2 ? cm : t2;
            }
#pragma unroll 2
            for (int j = 0; j < cm; j++) {
                ull ck = (j < cnt) ? buf[j * P1T + threadIdx.x] : ~0ull;
                insertK(key, ck);
            }
        }
    }

    // Merge the four strips through smem.
    __syncthreads();
    ull* pairs = (ull*)smem_raw;         // 24 KB needed, tile/buf dead now
    if (s > 0) {
#pragma unroll
        for (int j = 0; j < KNN; j++)
            pairs[((s - 1) * QPB + lq) * KNN + j] = key[j];
    }
    __syncthreads();

    if (s == 0) {
#pragma unroll 1
        for (int s2 = 0; s2 < STRIPS - 1; s2++)
#pragma unroll
            for (int j = 0; j < KNN; j++)
                insertK(key, pairs[(s2 * QPB + lq) * KNN + j]);

        int4* kp = (int4*)(g_knn + ((size_t)b * NPTS + n) * KNN);
        kp[0] = make_int4((int)(unsigned)key[0],  (int)(unsigned)key[1],
                          (int)(unsigned)key[2],  (int)(unsigned)key[3]);
        kp[1] = make_int4((int)(unsigned)key[4],  (int)(unsigned)key[5],
                          (int)(unsigned)key[6],  (int)(unsigned)key[7]);
        kp[2] = make_int4((int)(unsigned)key[8],  (int)(unsigned)key[9],
                          (int)(unsigned)key[10], (int)(unsigned)key[11]);
        kp[3] = make_int4((int)(unsigned)key[12], (int)(unsigned)key[13],
                          (int)(unsigned)key[14], (int)(unsigned)key[15]);
    }
}

// ---------------- Phase 2: MLP + staged transpose-add epilogue --------------
// Thread = (n, kp, eh): 2 points (k = kh*8+kp, +4), half the output columns.
// Per d-row: 8 broadcast LDS.128 feed 2x16 FFMA2 -> 4x less L1 per point.
#define MLP_SMEM_FLOATS (DDIM*DDIM + 4*DDIM + DDIM + 128*DDIM)

extern "C" __global__ void __launch_bounds__(128, 4)
mlp_kernel(const float* __restrict__ xyz, const float* __restrict__ x,
           const float* __restrict__ W1, const float* __restrict__ b1,
           const float* __restrict__ W2, const float* __restrict__ b2,
           float* __restrict__ out)
{
    extern __shared__ float sm[];
    float*  W2s = sm;                                // 4096
    float4* W1p = (float4*)(sm + DDIM*DDIM);         // 64 float4
    float*  b2s = sm + DDIM*DDIM + 4*DDIM;           // 64
    float*  stg = sm + DDIM*DDIM + 4*DDIM + DDIM;    // 128 x 64 staging

    int tid = threadIdx.x;
    for (int i = tid; i < DDIM*DDIM; i += 128) W2s[i] = W2[i];
    if (tid < DDIM) {
        W1p[tid] = make_float4(W1[tid], W1[DDIM + tid], W1[2*DDIM + tid], b1[tid]);
        b2s[tid] = b2[tid];
    }
    __syncthreads();

    int kh = blockIdx.x & 1;
    int nt = (blockIdx.x >> 1) & 255;
    int b  = blockIdx.x >> 9;
    int j  = tid & 15;                 // n within tile
    int kp = (tid >> 4) & 3;           // k-pair id
    int eh = tid >> 6;                 // output-column half (warp-uniform)
    int n  = nt * 16 + j;

    const int* kr = g_knn + (((size_t)b * NPTS + n) << 4) + kh * 8 + kp;
    int mA = kr[0];
    int mB = kr[4];
    const float* xb = xyz + (size_t)b * NPTS * 3;
    float px = xb[3*n], py = xb[3*n+1], pz = xb[3*n+2];
    float dxA = px - xb[3*mA], dyA = py - xb[3*mA+1], dzA = pz - xb[3*mA+2];
    float dxB = px - xb[3*mB], dyB = py - xb[3*mB+1], dzB = pz - xb[3*mB+2];

    ull accA[16], accB[16];
    const ull* b2p = (const ull*)(b2s + (eh << 5));
#pragma unroll
    for (int e = 0; e < 16; e++) { accA[e] = b2p[e]; accB[e] = b2p[e]; }

#pragma unroll 4
    for (int d = 0; d < DDIM; d++) {
        float4 w1 = W1p[d];
        float hA = fmaf(dzA, w1.z, fmaf(dyA, w1.y, fmaf(dxA, w1.x, w1.w)));
        float hB = fmaf(dzB, w1.z, fmaf(dyB, w1.y, fmaf(dxB, w1.x, w1.w)));
        hA = fmaxf(hA, 0.0f);
        hB = fmaxf(hB, 0.0f);
        if (__all_sync(0xffffffffu, (hA == 0.0f) && (hB == 0.0f))) continue;
        ull h2A, h2B;
        asm("mov.b64 %0, {%1, %1};" : "=l"(h2A) : "r"(__float_as_int(hA)));
        asm("mov.b64 %0, {%1, %1};" : "=l"(h2B) : "r"(__float_as_int(hB)));
        const ulonglong2* w = (const ulonglong2*)(W2s + (d << 6) + (eh << 5));
#pragma unroll
        for (int e = 0; e < 8; e++) {
            ulonglong2 wv = w[e];   // broadcast LDS.128
            asm("fma.rn.f32x2 %0, %1, %2, %0;" : "+l"(accA[2*e])   : "l"(h2A), "l"(wv.x));
            asm("fma.rn.f32x2 %0, %1, %2, %0;" : "+l"(accA[2*e+1]) : "l"(h2A), "l"(wv.y));
            asm("fma.rn.f32x2 %0, %1, %2, %0;" : "+l"(accB[2*e])   : "l"(h2B), "l"(wv.x));
            asm("fma.rn.f32x2 %0, %1, %2, %0;" : "+l"(accB[2*e+1]) : "l"(h2B), "l"(wv.y));
        }
    }

    // Stage both points' half-rows (XOR-swizzled float4 columns).
    ulonglong2* st2 = (ulonglong2*)stg;
    int rA = kp * 16 + j;                // staging row = k_local*16 + n
    int rB = (kp + 4) * 16 + j;
#pragma unroll
    for (int e = 0; e < 8; e++) {
        int c4 = (eh << 3) + e;
        ulonglong2 vA; vA.x = accA[2*e]; vA.y = accA[2*e+1];
        ulonglong2 vB; vB.x = accB[2*e]; vB.y = accB[2*e+1];
        st2[rA * 16 + (c4 ^ (rA & 15))] = vA;
        st2[rB * 16 + (c4 ^ (rB & 15))] = vB;
    }
    __syncthreads();

    // Coalesced flush: out[b,k,n,:] = x[b,k,n,:] + pos_enc.
    const ulonglong2* xg = (const ulonglong2*)x;
    ulonglong2*       og = (ulonglong2*)out;
#pragma unroll
    for (int i = 0; i < 16; i++) {
        int f    = tid + 128 * i;
        int c4   = f & 15;
        int row  = f >> 4;
        int kk   = kh * 8 + (row >> 4);
        int jj   = row & 15;
        ulonglong2 pv = st2[row * 16 + (c4 ^ (row & 15))];
        size_t gi = ((((size_t)b * KNN + kk) * NPTS) + nt * 16 + jj) * 16 + c4;
        ulonglong2 xv = xg[gi];
        ulonglong2 r;
        asm("add.rn.f32x2 %0, %1, %2;" : "=l"(r.x) : "l"(pv.x), "l"(xv.x));
        asm("add.rn.f32x2 %0, %1, %2;" : "=l"(r.y) : "l"(pv.y), "l"(xv.y));
        og[gi] = r;
    }
}

extern "C" void kernel_launch(void* const* d_in, const int* in_sizes, int n_in,
                              void* d_out, int out_size) {
    const float* xyz = (const float*)d_in[0];
    const float* x   = (const float*)d_in[1];
    const float* W1  = (const float*)d_in[2];
    const float* b1  = (const float*)d_in[3];
    const float* W2  = (const float*)d_in[4];
    const float* b2  = (const float*)d_in[5];
    float* out = (float*)d_out;

    cudaFuncSetAttribute(knn_kernel, cudaFuncAttributeMaxDynamicSharedMemorySize,
                         KNN_SMEM);
    cudaFuncSetAttribute(mlp_kernel, cudaFuncAttributeMaxDynamicSharedMemorySize,
                         MLP_SMEM_FLOATS * (int)sizeof(float));

    knn_kernel<<<BDIM * NPTS / QPB, P1T, KNN_SMEM>>>(xyz);
    mlp_kernel<<<BDIM * 256 * 2, 128, MLP_SMEM_FLOATS * sizeof(float)>>>(
        xyz, x, W1, b1, W2, b2, out);
}

// round 6
// speedup vs baseline: 1.1675x; 1.1675x over previous
#include <cuda_runtime.h>

#define BDIM 8
#define NPTS 4096
#define DDIM 64
#define KNN 16
#define QPB 64                           // queries per phase-1 block
#define STRIPS 2
#define P1T (QPB * STRIPS)               // 128 threads
#define TILE 512                         // candidates per smem tile
#define NT (NPTS / TILE)                 // 8 tiles
#define SLICE (TILE / STRIPS)            // 256 candidates per strip per tile
#define DEPTH 32                         // smem buffer slots per thread
#define SEED 64

typedef unsigned long long ull;

__device__ int g_knn[BDIM * NPTS * KNN];   // 2 MB knn indices

// key = (float_bits(d) << 32) | idx. d >= 0 in practice (validated R1..R5,
// identical rel_err with/without sign transform) so unsigned compare ==
// exact lexicographic (d, idx) == jnp stable argsort order.
__device__ __forceinline__ ull packK(float d, int m) {
    return ((ull)(unsigned)__float_as_uint(d) << 32) | (unsigned)m;
}

__device__ __forceinline__ void insertK(ull (&key)[KNN], ull ck) {
#pragma unroll
    for (int j = 0; j < KNN; j++) {
        bool lt = ck < key[j];
        ull o = key[j];
        key[j] = lt ? ck : o;
        ck     = lt ? o  : ck;
    }
}

__device__ __forceinline__ float pdist(float4 q, float4 c) {
    float t = q.x * c.x;
    t = fmaf(q.y, c.y, t);
    t = fmaf(q.z, c.z, t);
    return fmaf(-2.0f, t, q.w + c.w);   // identical fp order to passing rounds
}

// ---------------- Phase 1: fused distance + exact top-16 --------------------
// 512 blocks x 128 threads = 64 queries x 2 strips. Candidates streamed in
// 512-pt smem tiles. Scan loop is FULLY convergent: accept -> predicated
// st.shared (inline PTX, no branch). Drain once per tile slice with warp-max
// trip count. Rare per-lane buffer overflow falls back to direct insert.
#define KNN_SMEM (TILE*16 + TILE*12 + DEPTH*P1T*8)   // 8K + 6K + 32K = 46K

extern "C" __global__ void __launch_bounds__(P1T)
knn_kernel(const float* __restrict__ xyz)
{
    extern __shared__ char smem_raw[];
    float4* cand = (float4*)smem_raw;                          // [TILE]
    float*  raw  = (float*)(smem_raw + TILE * 16);             // [TILE*3]
    ull*    buf  = (ull*)(smem_raw + TILE * 16 + TILE * 12);   // [DEPTH][P1T]

    int b  = blockIdx.x >> 6;            // 64 blocks per batch
    int n0 = (blockIdx.x & 63) * QPB;
    const float* xb = xyz + (size_t)b * NPTS * 3;

    int lq = threadIdx.x & (QPB - 1);
    int s  = threadIdx.x >> 6;           // strip 0/1 (warp-uniform)
    int n  = n0 + lq;

    float qx = xb[3*n], qy = xb[3*n+1], qz = xb[3*n+2];
    float qw = qx*qx; qw = fmaf(qy, qy, qw); qw = fmaf(qz, qz, qw);
    float4 q = make_float4(qx, qy, qz, qw);

    ull key[KNN];
#pragma unroll
    for (int j = 0; j < KNN; j++) key[j] = ~0ull;

    unsigned bufA = (unsigned)__cvta_generic_to_shared(buf) + threadIdx.x * 8u;

#pragma unroll 1
    for (int t = 0; t < NT; t++) {
        int p0 = t * TILE;
        __syncthreads();                 // previous tile fully consumed
        for (int i = threadIdx.x; i < TILE * 3; i += P1T)
            raw[i] = xb[p0 * 3 + i];
        __syncthreads();
        for (int p = threadIdx.x; p < TILE; p += P1T) {
            float cx = raw[3*p], cy = raw[3*p+1], cz = raw[3*p+2];
            float cw = cx*cx; cw = fmaf(cy, cy, cw); cw = fmaf(cz, cz, cw);
            cand[p] = make_float4(cx, cy, cz, cw);
        }
        __syncthreads();

        int c0 = s * SLICE;              // this strip's slice of the tile
        int m0 = p0 + c0;
        int start = 0;

        if (t == 0) {                    // seed: guarded direct inserts
#pragma unroll 1
            for (int i = 0; i < SEED; i++) {
                ull ck = packK(pdist(q, cand[c0 + i]), m0 + i);
                if (ck < key[KNN - 1]) insertK(key, ck);
            }
            start = SEED;
        }

        float thr = __uint_as_float((unsigned)(key[KNN - 1] >> 32));
        int cnt = 0;
#pragma unroll 4
        for (int i = start; i < SLICE; i++) {
            float d = pdist(q, cand[c0 + i]);
            int m = m0 + i;
            bool hit = (d <= thr);       // <= keeps tie exactness
            unsigned pr = hit & (cnt < DEPTH);
            if (hit & (cnt >= DEPTH))    // ~never taken; keeps exactness
                insertK(key, packK(d, m));
            unsigned a = bufA + ((unsigned)(pr ? cnt : 0) << 10);  // *P1T*8
            asm volatile(
                "{\n\t.reg .pred p;\n\t"
                "setp.ne.u32 p, %0, 0;\n\t"
                "@p st.shared.v2.u32 [%1], {%2, %3};\n\t}"
                :: "r"(pr), "r"(a), "r"((unsigned)m), "r"(__float_as_uint(d))
                : "memory");
            cnt += pr;
        }
        int cm = cnt;                    // convergent warp-max trip count
#pragma unroll
        for (int o = 16; o > 0; o >>= 1) {
            int t2 = __shfl_xor_sync(0xffffffffu, cm, o);
            cm = cm > t2 ? cm : t2;
        }
#pragma unroll 2
        for (int j = 0; j < cm; j++) {
            ull ck = (j < cnt) ? buf[j * P1T + threadIdx.x] : ~0ull;
            insertK(key, ck);
        }
    }

    // Merge the two strips through smem.
    __syncthreads();
    ull* pairs = (ull*)smem_raw;         // 8 KB needed; tile/buf dead now
    if (s == 1) {
#pragma unroll
        for (int j = 0; j < KNN; j++) pairs[lq * KNN + j] = key[j];
    }
    __syncthreads();

    if (s == 0) {
#pragma unroll
        for (int j = 0; j < KNN; j++) insertK(key, pairs[lq * KNN + j]);

        int4* kp = (int4*)(g_knn + ((size_t)b * NPTS + n) * KNN);
        kp[0] = make_int4((int)(unsigned)key[0],  (int)(unsigned)key[1],
                          (int)(unsigned)key[2],  (int)(unsigned)key[3]);
        kp[1] = make_int4((int)(unsigned)key[4],  (int)(unsigned)key[5],
                          (int)(unsigned)key[6],  (int)(unsigned)key[7]);
        kp[2] = make_int4((int)(unsigned)key[8],  (int)(unsigned)key[9],
                          (int)(unsigned)key[10], (int)(unsigned)key[11]);
        kp[3] = make_int4((int)(unsigned)key[12], (int)(unsigned)key[13],
                          (int)(unsigned)key[14], (int)(unsigned)key[15]);
    }
}

// ---------------- Phase 2: MLP + staged transpose-add epilogue --------------
// Thread = (n=j, q, eh): 4 points (k = kh*8 + {q,q+2,q+4,q+6}), quarter of the
// output columns (eh warp-uniform). Per d-row: 4 broadcast LDS.128 feed
// 4x8 FFMA2 -> 1 LDS.128 per point-row (was 4 in R5).
#define MLP_SMEM_FLOATS (DDIM*DDIM + 4*DDIM + DDIM + 128*DDIM)

extern "C" __global__ void __launch_bounds__(128, 4)
mlp_kernel(const float* __restrict__ xyz, const float* __restrict__ x,
           const float* __restrict__ W1, const float* __restrict__ b1,
           const float* __restrict__ W2, const float* __restrict__ b2,
           float* __restrict__ out)
{
    extern __shared__ float sm[];
    float*  W2s = sm;                                // 4096
    float4* W1p = (float4*)(sm + DDIM*DDIM);         // 64 float4
    float*  b2s = sm + DDIM*DDIM + 4*DDIM;           // 64
    float*  stg = sm + DDIM*DDIM + 4*DDIM + DDIM;    // 128 x 64 staging

    int tid = threadIdx.x;
    for (int i = tid; i < DDIM*DDIM; i += 128) W2s[i] = W2[i];
    if (tid < DDIM) {
        W1p[tid] = make_float4(W1[tid], W1[DDIM + tid], W1[2*DDIM + tid], b1[tid]);
        b2s[tid] = b2[tid];
    }
    __syncthreads();

    int kh = blockIdx.x & 1;
    int nt = (blockIdx.x >> 1) & 255;
    int b  = blockIdx.x >> 9;
    int j  = tid & 15;                 // n within tile
    int qp = (tid >> 4) & 1;           // k-parity
    int eh = tid >> 5;                 // output-column quarter (warp-uniform)
    int n  = nt * 16 + j;

    const int* kr = g_knn + (((size_t)b * NPTS + n) << 4) + kh * 8 + qp;
    const float* xb = xyz + (size_t)b * NPTS * 3;
    float px = xb[3*n], py = xb[3*n+1], pz = xb[3*n+2];

    float dx[4], dy[4], dz[4];
#pragma unroll
    for (int u = 0; u < 4; u++) {
        int m = kr[2 * u];
        dx[u] = px - xb[3*m];
        dy[u] = py - xb[3*m+1];
        dz[u] = pz - xb[3*m+2];
    }

    ull acc[4][8];
    const ull* b2p = (const ull*)(b2s + (eh << 4));
#pragma unroll
    for (int u = 0; u < 4; u++)
#pragma unroll
        for (int e = 0; e < 8; e++) acc[u][e] = b2p[e];

#pragma unroll 4
    for (int d = 0; d < DDIM; d++) {
        float4 w1 = W1p[d];
        float h[4];
        unsigned z = 1;
#pragma unroll
        for (int u = 0; u < 4; u++) {
            h[u] = fmaf(dz[u], w1.z, fmaf(dy[u], w1.y, fmaf(dx[u], w1.x, w1.w)));
            h[u] = fmaxf(h[u], 0.0f);
            z &= (h[u] == 0.0f);
        }
        if (__all_sync(0xffffffffu, z)) continue;   // dead ReLU row skip
        ull h2[4];
#pragma unroll
        for (int u = 0; u < 4; u++)
            asm("mov.b64 %0, {%1, %1};" : "=l"(h2[u]) : "r"(__float_as_int(h[u])));
        const ulonglong2* w = (const ulonglong2*)(W2s + (d << 6) + (eh << 4));
#pragma unroll
        for (int e = 0; e < 4; e++) {
            ulonglong2 wv = w[e];   // broadcast LDS.128
#pragma unroll
            for (int u = 0; u < 4; u++) {
                asm("fma.rn.f32x2 %0, %1, %2, %0;" : "+l"(acc[u][2*e])   : "l"(h2[u]), "l"(wv.x));
                asm("fma.rn.f32x2 %0, %1, %2, %0;" : "+l"(acc[u][2*e+1]) : "l"(h2[u]), "l"(wv.y));
            }
        }
    }

    // Stage quarter-rows (XOR-swizzled float4 columns).
    ulonglong2* st2 = (ulonglong2*)stg;
#pragma unroll
    for (int u = 0; u < 4; u++) {
        int r = (qp + 2 * u) * 16 + j;      // staging row = k_local*16 + n
#pragma unroll
        for (int e = 0; e < 4; e++) {
            int c4 = (eh << 2) + e;
            ulonglong2 v; v.x = acc[u][2*e]; v.y = acc[u][2*e+1];
            st2[r * 16 + (c4 ^ (r & 15))] = v;
        }
    }
    __syncthreads();

    // Coalesced flush: out[b,k,n,:] = x[b,k,n,:] + pos_enc.
    const ulonglong2* xg = (const ulonglong2*)x;
    ulonglong2*       og = (ulonglong2*)out;
#pragma unroll
    for (int i = 0; i < 16; i++) {
        int f    = tid + 128 * i;
        int c4   = f & 15;
        int row  = f >> 4;
        int kk   = kh * 8 + (row >> 4);
        int jj   = row & 15;
        ulonglong2 pv = st2[row * 16 + (c4 ^ (row & 15))];
        size_t gi = ((((size_t)b * KNN + kk) * NPTS) + nt * 16 + jj) * 16 + c4;
        ulonglong2 xv = xg[gi];
        ulonglong2 r;
        asm("add.rn.f32x2 %0, %1, %2;" : "=l"(r.x) : "l"(pv.x), "l"(xv.x));
        asm("add.rn.f32x2 %0, %1, %2;" : "=l"(r.y) : "l"(pv.y), "l"(xv.y));
        og[gi] = r;
    }
}

extern "C" void kernel_launch(void* const* d_in, const int* in_sizes, int n_in,
                              void* d_out, int out_size) {
    const float* xyz = (const float*)d_in[0];
    const float* x   = (const float*)d_in[1];
    const float* W1  = (const float*)d_in[2];
    const float* b1  = (const float*)d_in[3];
    const float* W2  = (const float*)d_in[4];
    const float* b2  = (const float*)d_in[5];
    float* out = (float*)d_out;

    cudaFuncSetAttribute(knn_kernel, cudaFuncAttributeMaxDynamicSharedMemorySize,
                         KNN_SMEM);
    cudaFuncSetAttribute(mlp_kernel, cudaFuncAttributeMaxDynamicSharedMemorySize,
                         MLP_SMEM_FLOATS * (int)sizeof(float));

    knn_kernel<<<BDIM * NPTS / QPB, P1T, KNN_SMEM>>>(xyz);
    mlp_kernel<<<BDIM * 256 * 2, 128, MLP_SMEM_FLOATS * sizeof(float)>>>(
        xyz, x, W1, b1, W2, b2, out);
}

// round 7
// speedup vs baseline: 1.2291x; 1.0528x over previous
#include <cuda_runtime.h>

#define BDIM 8
#define NPTS 4096
#define DDIM 64
#define KNN 16
#define QPB 64                           // queries per phase-1 block
#define STRIPS 2
#define P1T (QPB * STRIPS)               // 128 threads
#define TILE 512                         // candidates per smem tile
#define NT (NPTS / TILE)                 // 8 tiles
#define SLICE (TILE / STRIPS)            // 256 candidates per strip per tile
#define DEPTH 32                         // smem buffer slots per thread
#define SEED 64
#define GRP 8                            // scan group size (ILP width)

typedef unsigned long long ull;

__device__ int g_knn[BDIM * NPTS * KNN];   // 2 MB knn indices

// key = (float_bits(d) << 32) | idx. d >= 0 (validated R1..R6) so unsigned
// compare == exact lexicographic (d, idx) == jnp stable argsort order.
__device__ __forceinline__ ull packK(float d, int m) {
    return ((ull)(unsigned)__float_as_uint(d) << 32) | (unsigned)m;
}

__device__ __forceinline__ void insertK(ull (&key)[KNN], ull ck) {
#pragma unroll
    for (int j = 0; j < KNN; j++) {
        bool lt = ck < key[j];
        ull o = key[j];
        key[j] = lt ? ck : o;
        ck     = lt ? o  : ck;
    }
}

__device__ __forceinline__ float pdist(float4 q, float4 c) {
    float t = q.x * c.x;
    t = fmaf(q.y, c.y, t);
    t = fmaf(q.z, c.z, t);
    return fmaf(-2.0f, t, q.w + c.w);   // identical fp order to passing rounds
}

// ---------------- Phase 1: fused distance + exact top-16 --------------------
// 512 blocks x 128 threads = 64 queries x 2 strips. Candidates streamed in
// 512-pt smem tiles. Scan: groups of 8 independent distance chains (pipelined
// LDS broadcasts), then 8 predicated st.shared WITHOUT memory clobber so the
// next group's loads hoist above them. Convergent warp-max drain per slice.
#define KNN_SMEM (TILE*16 + TILE*12 + DEPTH*P1T*8)   // 8K + 6K + 32K = 46K

extern "C" __global__ void __launch_bounds__(P1T)
knn_kernel(const float* __restrict__ xyz)
{
    extern __shared__ char smem_raw[];
    float4* cand = (float4*)smem_raw;                          // [TILE]
    float*  raw  = (float*)(smem_raw + TILE * 16);             // [TILE*3]
    ull*    buf  = (ull*)(smem_raw + TILE * 16 + TILE * 12);   // [DEPTH][P1T]

    int b  = blockIdx.x >> 6;            // 64 blocks per batch
    int n0 = (blockIdx.x & 63) * QPB;
    const float* xb = xyz + (size_t)b * NPTS * 3;

    int lq = threadIdx.x & (QPB - 1);
    int s  = threadIdx.x >> 6;           // strip 0/1 (warp-uniform)
    int n  = n0 + lq;

    float qx = xb[3*n], qy = xb[3*n+1], qz = xb[3*n+2];
    float qw = qx*qx; qw = fmaf(qy, qy, qw); qw = fmaf(qz, qz, qw);
    float4 q = make_float4(qx, qy, qz, qw);

    ull key[KNN];
#pragma unroll
    for (int j = 0; j < KNN; j++) key[j] = ~0ull;

    unsigned bufA = (unsigned)__cvta_generic_to_shared(buf) + threadIdx.x * 8u;

#pragma unroll 1
    for (int t = 0; t < NT; t++) {
        int p0 = t * TILE;
        __syncthreads();                 // previous tile fully consumed
        for (int i = threadIdx.x; i < TILE * 3; i += P1T)
            raw[i] = xb[p0 * 3 + i];
        __syncthreads();
        for (int p = threadIdx.x; p < TILE; p += P1T) {
            float cx = raw[3*p], cy = raw[3*p+1], cz = raw[3*p+2];
            float cw = cx*cx; cw = fmaf(cy, cy, cw); cw = fmaf(cz, cz, cw);
            cand[p] = make_float4(cx, cy, cz, cw);
        }
        __syncthreads();

        int c0 = s * SLICE;              // this strip's slice of the tile
        int m0 = p0 + c0;
        int start = 0;

        if (t == 0) {                    // seed: guarded direct inserts
#pragma unroll 1
            for (int i = 0; i < SEED; i++) {
                ull ck = packK(pdist(q, cand[c0 + i]), m0 + i);
                if (ck < key[KNN - 1]) insertK(key, ck);
            }
            start = SEED;
        }

        float thr = __uint_as_float((unsigned)(key[KNN - 1] >> 32));
        int cnt = 0;
#pragma unroll 1
        for (int i0 = start; i0 < SLICE; i0 += GRP) {
            float dv[GRP];
#pragma unroll
            for (int u = 0; u < GRP; u++)      // 8 independent LDS+FMA chains
                dv[u] = pdist(q, cand[c0 + i0 + u]);
#pragma unroll
            for (int u = 0; u < GRP; u++) {
                float d = dv[u];
                int m = m0 + i0 + u;
                bool hit = (d <= thr);         // <= keeps tie exactness
                unsigned pr = hit & (cnt < DEPTH);
                if (hit & (cnt >= DEPTH))      // ~never taken; exactness
                    insertK(key, packK(d, m));
                unsigned a = bufA + ((unsigned)(pr ? cnt : 0) << 10); // *P1T*8
                asm volatile(                  // NO memory clobber: loads of
                    "{\n\t.reg .pred p;\n\t"   // the next group may hoist
                    "setp.ne.u32 p, %0, 0;\n\t"
                    "@p st.shared.v2.u32 [%1], {%2, %3};\n\t}"
                    :: "r"(pr), "r"(a), "r"((unsigned)m), "r"(__float_as_uint(d)));
                cnt += pr;
            }
        }
        asm volatile("" ::: "memory");   // order asm stores before C++ reads
        __syncwarp();

        int cm = cnt;                    // convergent warp-max trip count
#pragma unroll
        for (int o = 16; o > 0; o >>= 1) {
            int t2 = __shfl_xor_sync(0xffffffffu, cm, o);
            cm = cm > t2 ? cm : t2;
        }
#pragma unroll 2
        for (int j = 0; j < cm; j++) {
            ull ck = (j < cnt) ? buf[j * P1T + threadIdx.x] : ~0ull;
            insertK(key, ck);
        }
    }

    // Merge the two strips through smem.
    __syncthreads();
    ull* pairs = (ull*)smem_raw;         // 8 KB needed; tile/buf dead now
    if (s == 1) {
#pragma unroll
        for (int j = 0; j < KNN; j++) pairs[lq * KNN + j] = key[j];
    }
    __syncthreads();

    if (s == 0) {
#pragma unroll
        for (int j = 0; j < KNN; j++) insertK(key, pairs[lq * KNN + j]);

        int4* kp = (int4*)(g_knn + ((size_t)b * NPTS + n) * KNN);
        kp[0] = make_int4((int)(unsigned)key[0],  (int)(unsigned)key[1],
                          (int)(unsigned)key[2],  (int)(unsigned)key[3]);
        kp[1] = make_int4((int)(unsigned)key[4],  (int)(unsigned)key[5],
                          (int)(unsigned)key[6],  (int)(unsigned)key[7]);
        kp[2] = make_int4((int)(unsigned)key[8],  (int)(unsigned)key[9],
                          (int)(unsigned)key[10], (int)(unsigned)key[11]);
        kp[3] = make_int4((int)(unsigned)key[12], (int)(unsigned)key[13],
                          (int)(unsigned)key[14], (int)(unsigned)key[15]);
    }
}

// ---------------- Phase 2: MLP + staged transpose-add epilogue --------------
// (byte-identical to round 6: 104.5 us measured)
#define MLP_SMEM_FLOATS (DDIM*DDIM + 4*DDIM + DDIM + 128*DDIM)

extern "C" __global__ void __launch_bounds__(128, 4)
mlp_kernel(const float* __restrict__ xyz, const float* __restrict__ x,
           const float* __restrict__ W1, const float* __restrict__ b1,
           const float* __restrict__ W2, const float* __restrict__ b2,
           float* __restrict__ out)
{
    extern __shared__ float sm[];
    float*  W2s = sm;                                // 4096
    float4* W1p = (float4*)(sm + DDIM*DDIM);         // 64 float4
    float*  b2s = sm + DDIM*DDIM + 4*DDIM;           // 64
    float*  stg = sm + DDIM*DDIM + 4*DDIM + DDIM;    // 128 x 64 staging

    int tid = threadIdx.x;
    for (int i = tid; i < DDIM*DDIM; i += 128) W2s[i] = W2[i];
    if (tid < DDIM) {
        W1p[tid] = make_float4(W1[tid], W1[DDIM + tid], W1[2*DDIM + tid], b1[tid]);
        b2s[tid] = b2[tid];
    }
    __syncthreads();

    int kh = blockIdx.x & 1;
    int nt = (blockIdx.x >> 1) & 255;
    int b  = blockIdx.x >> 9;
    int j  = tid & 15;                 // n within tile
    int qp = (tid >> 4) & 1;           // k-parity
    int eh = tid >> 5;                 // output-column quarter (warp-uniform)
    int n  = nt * 16 + j;

    const int* kr = g_knn + (((size_t)b * NPTS + n) << 4) + kh * 8 + qp;
    const float* xb = xyz + (size_t)b * NPTS * 3;
    float px = xb[3*n], py = xb[3*n+1], pz = xb[3*n+2];

    float dx[4], dy[4], dz[4];
#pragma unroll
    for (int u = 0; u < 4; u++) {
        int m = kr[2 * u];
        dx[u] = px - xb[3*m];
        dy[u] = py - xb[3*m+1];
        dz[u] = pz - xb[3*m+2];
    }

    ull acc[4][8];
    const ull* b2p = (const ull*)(b2s + (eh << 4));
#pragma unroll
    for (int u = 0; u < 4; u++)
#pragma unroll
        for (int e = 0; e < 8; e++) acc[u][e] = b2p[e];

#pragma unroll 4
    for (int d = 0; d < DDIM; d++) {
        float4 w1 = W1p[d];
        float h[4];
        unsigned z = 1;
#pragma unroll
        for (int u = 0; u < 4; u++) {
            h[u] = fmaf(dz[u], w1.z, fmaf(dy[u], w1.y, fmaf(dx[u], w1.x, w1.w)));
            h[u] = fmaxf(h[u], 0.0f);
            z &= (h[u] == 0.0f);
        }
        if (__all_sync(0xffffffffu, z)) continue;   // dead ReLU row skip
        ull h2[4];
#pragma unroll
        for (int u = 0; u < 4; u++)
            asm("mov.b64 %0, {%1, %1};" : "=l"(h2[u]) : "r"(__float_as_int(h[u])));
        const ulonglong2* w = (const ulonglong2*)(W2s + (d << 6) + (eh << 4));
#pragma unroll
        for (int e = 0; e < 4; e++) {
            ulonglong2 wv = w[e];   // broadcast LDS.128
#pragma unroll
            for (int u = 0; u < 4; u++) {
                asm("fma.rn.f32x2 %0, %1, %2, %0;" : "+l"(acc[u][2*e])   : "l"(h2[u]), "l"(wv.x));
                asm("fma.rn.f32x2 %0, %1, %2, %0;" : "+l"(acc[u][2*e+1]) : "l"(h2[u]), "l"(wv.y));
            }
        }
    }

    // Stage quarter-rows (XOR-swizzled float4 columns).
    ulonglong2* st2 = (ulonglong2*)stg;
#pragma unroll
    for (int u = 0; u < 4; u++) {
        int r = (qp + 2 * u) * 16 + j;      // staging row = k_local*16 + n
#pragma unroll
        for (int e = 0; e < 4; e++) {
            int c4 = (eh << 2) + e;
            ulonglong2 v; v.x = acc[u][2*e]; v.y = acc[u][2*e+1];
            st2[r * 16 + (c4 ^ (r & 15))] = v;
        }
    }
    __syncthreads();

    // Coalesced flush: out[b,k,n,:] = x[b,k,n,:] + pos_enc.
    const ulonglong2* xg = (const ulonglong2*)x;
    ulonglong2*       og = (ulonglong2*)out;
#pragma unroll
    for (int i = 0; i < 16; i++) {
        int f    = tid + 128 * i;
        int c4   = f & 15;
        int row  = f >> 4;
        int kk   = kh * 8 + (row >> 4);
        int jj   = row & 15;
        ulonglong2 pv = st2[row * 16 + (c4 ^ (row & 15))];
        size_t gi = ((((size_t)b * KNN + kk) * NPTS) + nt * 16 + jj) * 16 + c4;
        ulonglong2 xv = xg[gi];
        ulonglong2 r;
        asm("add.rn.f32x2 %0, %1, %2;" : "=l"(r.x) : "l"(pv.x), "l"(xv.x));
        asm("add.rn.f32x2 %0, %1, %2;" : "=l"(r.y) : "l"(pv.y), "l"(xv.y));
        og[gi] = r;
    }
}

extern "C" void kernel_launch(void* const* d_in, const int* in_sizes, int n_in,
                              void* d_out, int out_size) {
    const float* xyz = (const float*)d_in[0];
    const float* x   = (const float*)d_in[1];
    const float* W1  = (const float*)d_in[2];
    const float* b1  = (const float*)d_in[3];
    const float* W2  = (const float*)d_in[4];
    const float* b2  = (const float*)d_in[5];
    float* out = (float*)d_out;

    cudaFuncSetAttribute(knn_kernel, cudaFuncAttributeMaxDynamicSharedMemorySize,
                         KNN_SMEM);
    cudaFuncSetAttribute(mlp_kernel, cudaFuncAttributeMaxDynamicSharedMemorySize,
                         MLP_SMEM_FLOATS * (int)sizeof(float));

    knn_kernel<<<BDIM * NPTS / QPB, P1T, KNN_SMEM>>>(xyz);
    mlp_kernel<<<BDIM * 256 * 2, 128, MLP_SMEM_FLOATS * sizeof(float)>>>(
        xyz, x, W1, b1, W2, b2, out);
}

// round 8
// speedup vs baseline: 1.3033x; 1.0603x over previous
#include <cuda_runtime.h>

#define BDIM 8
#define NPTS 4096
#define DDIM 64
#define KNN 16
#define QPB 32                           // queries per phase-1 block
#define STRIPS 4
#define P1T (QPB * STRIPS)               // 128 threads
#define TILE 512                         // candidates per smem tile
#define NT (NPTS / TILE)                 // 8 tiles
#define SLICE (TILE / STRIPS)            // 128 candidates per strip per tile
#define DEPTH 16                         // smem buffer slots per thread
#define SEED 64
#define GRP 8                            // scan group size (ILP width)

typedef unsigned long long ull;

__device__ int g_knn[BDIM * NPTS * KNN];   // 2 MB knn indices

// key = (float_bits(d) << 32) | idx. d >= 0 (validated R1..R7) so unsigned
// compare == exact lexicographic (d, idx) == jnp stable argsort order.
__device__ __forceinline__ ull packK(float d, int m) {
    return ((ull)(unsigned)__float_as_uint(d) << 32) | (unsigned)m;
}

__device__ __forceinline__ void insertK(ull (&key)[KNN], ull ck) {
#pragma unroll
    for (int j = 0; j < KNN; j++) {
        bool lt = ck < key[j];
        ull o = key[j];
        key[j] = lt ? ck : o;
        ck     = lt ? o  : ck;
    }
}

__device__ __forceinline__ float pdist(float4 q, float4 c) {
    float t = q.x * c.x;
    t = fmaf(q.y, c.y, t);
    t = fmaf(q.z, c.z, t);
    return fmaf(-2.0f, t, q.w + c.w);   // identical fp order to passing rounds
}

// ---------------- Phase 1: fused distance + exact top-16 --------------------
// 1024 blocks x 128 threads = 32 queries x 4 strips (one full chip wave,
// 7 blocks/SM). Candidates streamed in 512-pt smem tiles. Hot loop is fully
// branchless: predicated st.shared appends, overflow handled by a convergent
// group-level drain (which also re-tightens thr). Final drain + strip merge.
#define KNN_SMEM (TILE*16 + TILE*12 + DEPTH*P1T*8)   // 8K + 6K + 16K = 30K

extern "C" __global__ void __launch_bounds__(P1T)
knn_kernel(const float* __restrict__ xyz)
{
    extern __shared__ char smem_raw[];
    float4* cand = (float4*)smem_raw;                          // [TILE]
    float*  raw  = (float*)(smem_raw + TILE * 16);             // [TILE*3]
    ull*    buf  = (ull*)(smem_raw + TILE * 16 + TILE * 12);   // [DEPTH][P1T]

    int b  = blockIdx.x >> 7;            // 128 blocks per batch
    int n0 = (blockIdx.x & 127) * QPB;
    const float* xb = xyz + (size_t)b * NPTS * 3;

    int lq = threadIdx.x & (QPB - 1);
    int s  = threadIdx.x >> 5;           // strip 0..3 (warp-uniform)
    int n  = n0 + lq;

    float qx = xb[3*n], qy = xb[3*n+1], qz = xb[3*n+2];
    float qw = qx*qx; qw = fmaf(qy, qy, qw); qw = fmaf(qz, qz, qw);
    float4 q = make_float4(qx, qy, qz, qw);

    ull key[KNN];
#pragma unroll
    for (int j = 0; j < KNN; j++) key[j] = ~0ull;

    unsigned bufA = (unsigned)__cvta_generic_to_shared(buf) + threadIdx.x * 8u;
    int cnt = 0;
    float thr;

#pragma unroll 1
    for (int t = 0; t < NT; t++) {
        int p0 = t * TILE;
        __syncthreads();                 // previous tile fully consumed
        for (int i = threadIdx.x; i < TILE * 3; i += P1T)
            raw[i] = xb[p0 * 3 + i];
        __syncthreads();
        for (int p = threadIdx.x; p < TILE; p += P1T) {
            float cx = raw[3*p], cy = raw[3*p+1], cz = raw[3*p+2];
            float cw = cx*cx; cw = fmaf(cy, cy, cw); cw = fmaf(cz, cz, cw);
            cand[p] = make_float4(cx, cy, cz, cw);
        }
        __syncthreads();

        int c0 = s * SLICE;              // this strip's slice of the tile
        int m0 = p0 + c0;
        int start = 0;

        if (t == 0) {                    // seed: guarded direct inserts
#pragma unroll 1
            for (int i = 0; i < SEED; i++) {
                ull ck = packK(pdist(q, cand[c0 + i]), m0 + i);
                if (ck < key[KNN - 1]) insertK(key, ck);
            }
            start = SEED;
        }
        thr = __uint_as_float((unsigned)(key[KNN - 1] >> 32));

#pragma unroll 1
        for (int i0 = start; i0 < SLICE; i0 += GRP) {
            // Convergent overflow guard: drain + re-tighten thr (rare).
            if (__any_sync(0xffffffffu, cnt > DEPTH - GRP)) {
                asm volatile("" ::: "memory");
                int cm = cnt;
#pragma unroll
                for (int o = 16; o > 0; o >>= 1) {
                    int t2 = __shfl_xor_sync(0xffffffffu, cm, o);
                    cm = cm > t2 ? cm : t2;
                }
#pragma unroll 2
                for (int j = 0; j < cm; j++) {
                    ull ck = (j < cnt) ? buf[j * P1T + threadIdx.x] : ~0ull;
                    insertK(key, ck);
                }
                cnt = 0;
                thr = __uint_as_float((unsigned)(key[KNN - 1] >> 32));
            }

            float dv[GRP];
#pragma unroll
            for (int u = 0; u < GRP; u++)      // 8 independent LDS+FMA chains
                dv[u] = pdist(q, cand[c0 + i0 + u]);
#pragma unroll
            for (int u = 0; u < GRP; u++) {    // branchless predicated append
                float d = dv[u];
                unsigned hit = (d <= thr);     // <= keeps tie exactness
                unsigned a = bufA + ((unsigned)cnt << 10);   // cnt*P1T*8
                asm volatile(                  // no memory clobber: next
                    "{\n\t.reg .pred p;\n\t"   // group's loads may hoist
                    "setp.ne.u32 p, %0, 0;\n\t"
                    "@p st.shared.v2.u32 [%1], {%2, %3};\n\t}"
                    :: "r"(hit), "r"(a),
                       "r"((unsigned)(m0 + i0 + u)), "r"(__float_as_uint(d)));
                cnt += hit;
            }
        }
    }

    // Final drain.
    asm volatile("" ::: "memory");
    {
        int cm = cnt;
#pragma unroll
        for (int o = 16; o > 0; o >>= 1) {
            int t2 = __shfl_xor_sync(0xffffffffu, cm, o);
            cm = cm > t2 ? cm : t2;
        }
#pragma unroll 2
        for (int j = 0; j < cm; j++) {
            ull ck = (j < cnt) ? buf[j * P1T + threadIdx.x] : ~0ull;
            insertK(key, ck);
        }
    }

    // Merge the four strips through smem.
    __syncthreads();
    ull* pairs = (ull*)smem_raw;         // 12 KB needed; tile/buf dead now
    if (s > 0) {
#pragma unroll
        for (int j = 0; j < KNN; j++)
            pairs[((s - 1) * QPB + lq) * KNN + j] = key[j];
    }
    __syncthreads();

    if (s == 0) {
#pragma unroll 1
        for (int s2 = 0; s2 < STRIPS - 1; s2++)
#pragma unroll
            for (int j = 0; j < KNN; j++)
                insertK(key, pairs[(s2 * QPB + lq) * KNN + j]);

        int4* kp = (int4*)(g_knn + ((size_t)b * NPTS + n) * KNN);
        kp[0] = make_int4((int)(unsigned)key[0],  (int)(unsigned)key[1],
                          (int)(unsigned)key[2],  (int)(unsigned)key[3]);
        kp[1] = make_int4((int)(unsigned)key[4],  (int)(unsigned)key[5],
                          (int)(unsigned)key[6],  (int)(unsigned)key[7]);
        kp[2] = make_int4((int)(unsigned)key[8],  (int)(unsigned)key[9],
                          (int)(unsigned)key[10], (int)(unsigned)key[11]);
        kp[3] = make_int4((int)(unsigned)key[12], (int)(unsigned)key[13],
                          (int)(unsigned)key[14], (int)(unsigned)key[15]);
    }
}

// ---------------- Phase 2: MLP + staged transpose-add epilogue --------------
// (byte-identical to rounds 6/7: 104.5 us measured)
#define MLP_SMEM_FLOATS (DDIM*DDIM + 4*DDIM + DDIM + 128*DDIM)

extern "C" __global__ void __launch_bounds__(128, 4)
mlp_kernel(const float* __restrict__ xyz, const float* __restrict__ x,
           const float* __restrict__ W1, const float* __restrict__ b1,
           const float* __restrict__ W2, const float* __restrict__ b2,
           float* __restrict__ out)
{
    extern __shared__ float sm[];
    float*  W2s = sm;                                // 4096
    float4* W1p = (float4*)(sm + DDIM*DDIM);         // 64 float4
    float*  b2s = sm + DDIM*DDIM + 4*DDIM;           // 64
    float*  stg = sm + DDIM*DDIM + 4*DDIM + DDIM;    // 128 x 64 staging

    int tid = threadIdx.x;
    for (int i = tid; i < DDIM*DDIM; i += 128) W2s[i] = W2[i];
    if (tid < DDIM) {
        W1p[tid] = make_float4(W1[tid], W1[DDIM + tid], W1[2*DDIM + tid], b1[tid]);
        b2s[tid] = b2[tid];
    }
    __syncthreads();

    int kh = blockIdx.x & 1;
    int nt = (blockIdx.x >> 1) & 255;
    int b  = blockIdx.x >> 9;
    int j  = tid & 15;                 // n within tile
    int qp = (tid >> 4) & 1;           // k-parity
    int eh = tid >> 5;                 // output-column quarter (warp-uniform)
    int n  = nt * 16 + j;

    const int* kr = g_knn + (((size_t)b * NPTS + n) << 4) + kh * 8 + qp;
    const float* xb = xyz + (size_t)b * NPTS * 3;
    float px = xb[3*n], py = xb[3*n+1], pz = xb[3*n+2];

    float dx[4], dy[4], dz[4];
#pragma unroll
    for (int u = 0; u < 4; u++) {
        int m = kr[2 * u];
        dx[u] = px - xb[3*m];
        dy[u] = py - xb[3*m+1];
        dz[u] = pz - xb[3*m+2];
    }

    ull acc[4][8];
    const ull* b2p = (const ull*)(b2s + (eh << 4));
#pragma unroll
    for (int u = 0; u < 4; u++)
#pragma unroll
        for (int e = 0; e < 8; e++) acc[u][e] = b2p[e];

#pragma unroll 4
    for (int d = 0; d < DDIM; d++) {
        float4 w1 = W1p[d];
        float h[4];
        unsigned z = 1;
#pragma unroll
        for (int u = 0; u < 4; u++) {
            h[u] = fmaf(dz[u], w1.z, fmaf(dy[u], w1.y, fmaf(dx[u], w1.x, w1.w)));
            h[u] = fmaxf(h[u], 0.0f);
            z &= (h[u] == 0.0f);
        }
        if (__all_sync(0xffffffffu, z)) continue;   // dead ReLU row skip
        ull h2[4];
#pragma unroll
        for (int u = 0; u < 4; u++)
            asm("mov.b64 %0, {%1, %1};" : "=l"(h2[u]) : "r"(__float_as_int(h[u])));
        const ulonglong2* w = (const ulonglong2*)(W2s + (d << 6) + (eh << 4));
#pragma unroll
        for (int e = 0; e < 4; e++) {
            ulonglong2 wv = w[e];   // broadcast LDS.128
#pragma unroll
            for (int u = 0; u < 4; u++) {
                asm("fma.rn.f32x2 %0, %1, %2, %0;" : "+l"(acc[u][2*e])   : "l"(h2[u]), "l"(wv.x));
                asm("fma.rn.f32x2 %0, %1, %2, %0;" : "+l"(acc[u][2*e+1]) : "l"(h2[u]), "l"(wv.y));
            }
        }
    }

    // Stage quarter-rows (XOR-swizzled float4 columns).
    ulonglong2* st2 = (ulonglong2*)stg;
#pragma unroll
    for (int u = 0; u < 4; u++) {
        int r = (qp + 2 * u) * 16 + j;      // staging row = k_local*16 + n
#pragma unroll
        for (int e = 0; e < 4; e++) {
            int c4 = (eh << 2) + e;
            ulonglong2 v; v.x = acc[u][2*e]; v.y = acc[u][2*e+1];
            st2[r * 16 + (c4 ^ (r & 15))] = v;
        }
    }
    __syncthreads();

    // Coalesced flush: out[b,k,n,:] = x[b,k,n,:] + pos_enc.
    const ulonglong2* xg = (const ulonglong2*)x;
    ulonglong2*       og = (ulonglong2*)out;
#pragma unroll
    for (int i = 0; i < 16; i++) {
        int f    = tid + 128 * i;
        int c4   = f & 15;
        int row  = f >> 4;
        int kk   = kh * 8 + (row >> 4);
        int jj   = row & 15;
        ulonglong2 pv = st2[row * 16 + (c4 ^ (row & 15))];
        size_t gi = ((((size_t)b * KNN + kk) * NPTS) + nt * 16 + jj) * 16 + c4;
        ulonglong2 xv = xg[gi];
        ulonglong2 r;
        asm("add.rn.f32x2 %0, %1, %2;" : "=l"(r.x) : "l"(pv.x), "l"(xv.x));
        asm("add.rn.f32x2 %0, %1, %2;" : "=l"(r.y) : "l"(pv.y), "l"(xv.y));
        og[gi] = r;
    }
}

extern "C" void kernel_launch(void* const* d_in, const int* in_sizes, int n_in,
                              void* d_out, int out_size) {
    const float* xyz = (const float*)d_in[0];
    const float* x   = (const float*)d_in[1];
    const float* W1  = (const float*)d_in[2];
    const float* b1  = (const float*)d_in[3];
    const float* W2  = (const float*)d_in[4];
    const float* b2  = (const float*)d_in[5];
    float* out = (float*)d_out;

    cudaFuncSetAttribute(knn_kernel, cudaFuncAttributeMaxDynamicSharedMemorySize,
                         KNN_SMEM);
    cudaFuncSetAttribute(mlp_kernel, cudaFuncAttributeMaxDynamicSharedMemorySize,
                         MLP_SMEM_FLOATS * (int)sizeof(float));

    knn_kernel<<<BDIM * NPTS / QPB, P1T, KNN_SMEM>>>(xyz);
    mlp_kernel<<<BDIM * 256 * 2, 128, MLP_SMEM_FLOATS * sizeof(float)>>>(
        xyz, x, W1, b1, W2, b2, out);
}

// round 9
// speedup vs baseline: 1.3317x; 1.0218x over previous
#include <cuda_runtime.h>

#define BDIM 8
#define NPTS 4096
#define DDIM 64
#define KNN 16
#define QPB 32                           // queries per phase-1 block
#define STRIPS 4
#define P1T (QPB * STRIPS)               // 128 threads
#define TILE 512                         // candidates per smem tile
#define NT (NPTS / TILE)                 // 8 tiles
#define SLICE (TILE / STRIPS)            // 128 candidates per strip per tile
#define DEPTH 16                         // smem buffer slots per thread
#define GRP 8                            // scan group size (ILP width)

typedef unsigned long long ull;

__device__ int g_knn[BDIM * NPTS * KNN];   // 2 MB knn indices

// key = (float_bits(d) << 32) | idx. d >= 0 (validated R1..R8) so unsigned
// compare == exact lexicographic (d, idx) == jnp stable argsort order.
__device__ __forceinline__ ull packK(float d, int m) {
    return ((ull)(unsigned)__float_as_uint(d) << 32) | (unsigned)m;
}

__device__ __forceinline__ void insertK(ull (&key)[KNN], ull ck) {
#pragma unroll
    for (int j = 0; j < KNN; j++) {
        bool lt = ck < key[j];
        ull o = key[j];
        key[j] = lt ? ck : o;
        ck     = lt ? o  : ck;
    }
}

__device__ __forceinline__ float pdist(float4 q, float4 c) {
    float t = q.x * c.x;
    t = fmaf(q.y, c.y, t);
    t = fmaf(q.z, c.z, t);
    return fmaf(-2.0f, t, q.w + c.w);   // identical fp order to passing rounds
}

// ---------------- Phase 1: fused distance + exact top-16 --------------------
// 1024 blocks x 128 threads = 32 queries x 4 strips (one full wave, 7 blk/SM).
// Hot loop: 8 independent distance chains, 8 independent accept flags, a
// log-depth prefix tree for buffer offsets, 8 INDEPENDENT predicated STS.
// No serial per-candidate cnt chain. Overflow handled by convergent drains.
#define KNN_SMEM (TILE*16 + TILE*12 + DEPTH*P1T*8)   // 8K + 6K + 16K = 30K

extern "C" __global__ void __launch_bounds__(P1T)
knn_kernel(const float* __restrict__ xyz)
{
    extern __shared__ char smem_raw[];
    float4* cand = (float4*)smem_raw;                          // [TILE]
    float*  raw  = (float*)(smem_raw + TILE * 16);             // [TILE*3]
    ull*    buf  = (ull*)(smem_raw + TILE * 16 + TILE * 12);   // [DEPTH][P1T]

    int b  = blockIdx.x >> 7;            // 128 blocks per batch
    int n0 = (blockIdx.x & 127) * QPB;
    const float* xb = xyz + (size_t)b * NPTS * 3;

    int lq = threadIdx.x & (QPB - 1);
    int s  = threadIdx.x >> 5;           // strip 0..3 (warp-uniform)
    int n  = n0 + lq;

    float qx = xb[3*n], qy = xb[3*n+1], qz = xb[3*n+2];
    float qw = qx*qx; qw = fmaf(qy, qy, qw); qw = fmaf(qz, qz, qw);
    float4 q = make_float4(qx, qy, qz, qw);

    ull key[KNN];
#pragma unroll
    for (int j = 0; j < KNN; j++) key[j] = ~0ull;

    unsigned bufA = (unsigned)__cvta_generic_to_shared(buf) + threadIdx.x * 8u;
    int cnt = 0;
    float thr;

#pragma unroll 1
    for (int t = 0; t < NT; t++) {
        int p0 = t * TILE;
        __syncthreads();                 // previous tile fully consumed
        for (int i = threadIdx.x; i < TILE * 3; i += P1T)
            raw[i] = xb[p0 * 3 + i];
        __syncthreads();
        for (int p = threadIdx.x; p < TILE; p += P1T) {
            float cx = raw[3*p], cy = raw[3*p+1], cz = raw[3*p+2];
            float cw = cx*cx; cw = fmaf(cy, cy, cw); cw = fmaf(cz, cz, cw);
            cand[p] = make_float4(cx, cy, cz, cw);
        }
        __syncthreads();

        int c0 = s * SLICE;              // this strip's slice of the tile
        int m0 = p0 + c0;
        int start = 0;

        if (t == 0) {                    // seed: 16 convergent inserts
#pragma unroll 1
            for (int i = 0; i < KNN; i++)
                insertK(key, packK(pdist(q, cand[c0 + i]), m0 + i));
            start = KNN;
        }
        thr = __uint_as_float((unsigned)(key[KNN - 1] >> 32));

#pragma unroll 1
        for (int i0 = start; i0 < SLICE; i0 += GRP) {
            // Convergent overflow guard: drain + re-tighten thr.
            if (__any_sync(0xffffffffu, cnt > DEPTH - GRP)) {
                asm volatile("" ::: "memory");
                int cm = cnt;
#pragma unroll
                for (int o = 16; o > 0; o >>= 1) {
                    int t2 = __shfl_xor_sync(0xffffffffu, cm, o);
                    cm = cm > t2 ? cm : t2;
                }
#pragma unroll 2
                for (int j = 0; j < cm; j++) {
                    ull ck = (j < cnt) ? buf[j * P1T + threadIdx.x] : ~0ull;
                    insertK(key, ck);
                }
                cnt = 0;
                thr = __uint_as_float((unsigned)(key[KNN - 1] >> 32));
            }

            float dv[GRP];
#pragma unroll
            for (int u = 0; u < GRP; u++)      // 8 independent LDS+FMA chains
                dv[u] = pdist(q, cand[c0 + i0 + u]);

            unsigned h[GRP];
#pragma unroll
            for (int u = 0; u < GRP; u++)      // 8 independent accept flags
                h[u] = (dv[u] <= thr);         // <= keeps tie exactness

            // Log-depth prefix offsets (no serial cnt chain).
            unsigned o1 = h[0];
            unsigned s01 = h[0] + h[1], s23 = h[2] + h[3], s45 = h[4] + h[5];
            unsigned o2 = s01;
            unsigned o3 = s01 + h[2];
            unsigned o4 = s01 + s23;
            unsigned o5 = o4 + h[4];
            unsigned o6 = o4 + s45;
            unsigned o7 = o6 + h[6];
            unsigned tot = o7 + h[7];
            unsigned off[GRP] = {0, o1, o2, o3, o4, o5, o6, o7};

#pragma unroll
            for (int u = 0; u < GRP; u++) {    // 8 independent predicated STS
                unsigned a = bufA + ((unsigned)(cnt + off[u]) << 10); // *P1T*8
                asm volatile(
                    "{\n\t.reg .pred p;\n\t"
                    "setp.ne.u32 p, %0, 0;\n\t"
                    "@p st.shared.v2.u32 [%1], {%2, %3};\n\t}"
                    :: "r"(h[u]), "r"(a),
                       "r"((unsigned)(m0 + i0 + u)), "r"(__float_as_uint(dv[u])));
            }
            cnt += tot;
        }
    }

    // Final drain.
    asm volatile("" ::: "memory");
    {
        int cm = cnt;
#pragma unroll
        for (int o = 16; o > 0; o >>= 1) {
            int t2 = __shfl_xor_sync(0xffffffffu, cm, o);
            cm = cm > t2 ? cm : t2;
        }
#pragma unroll 2
        for (int j = 0; j < cm; j++) {
            ull ck = (j < cnt) ? buf[j * P1T + threadIdx.x] : ~0ull;
            insertK(key, ck);
        }
    }

    // Merge the four strips through smem.
    __syncthreads();
    ull* pairs = (ull*)smem_raw;         // 12 KB needed; tile/buf dead now
    if (s > 0) {
#pragma unroll
        for (int j = 0; j < KNN; j++)
            pairs[((s - 1) * QPB + lq) * KNN + j] = key[j];
    }
    __syncthreads();

    if (s == 0) {
#pragma unroll 1
        for (int s2 = 0; s2 < STRIPS - 1; s2++)
#pragma unroll
            for (int j = 0; j < KNN; j++)
                insertK(key, pairs[(s2 * QPB + lq) * KNN + j]);

        int4* kp = (int4*)(g_knn + ((size_t)b * NPTS + n) * KNN);
        kp[0] = make_int4((int)(unsigned)key[0],  (int)(unsigned)key[1],
                          (int)(unsigned)key[2],  (int)(unsigned)key[3]);
        kp[1] = make_int4((int)(unsigned)key[4],  (int)(unsigned)key[5],
                          (int)(unsigned)key[6],  (int)(unsigned)key[7]);
        kp[2] = make_int4((int)(unsigned)key[8],  (int)(unsigned)key[9],
                          (int)(unsigned)key[10], (int)(unsigned)key[11]);
        kp[3] = make_int4((int)(unsigned)key[12], (int)(unsigned)key[13],
                          (int)(unsigned)key[14], (int)(unsigned)key[15]);
    }
}

// ---------------- Phase 2: MLP + staged transpose-add epilogue --------------
// (byte-identical to rounds 6-8: ~104.4 us measured)
#define MLP_SMEM_FLOATS (DDIM*DDIM + 4*DDIM + DDIM + 128*DDIM)

extern "C" __global__ void __launch_bounds__(128, 4)
mlp_kernel(const float* __restrict__ xyz, const float* __restrict__ x,
           const float* __restrict__ W1, const float* __restrict__ b1,
           const float* __restrict__ W2, const float* __restrict__ b2,
           float* __restrict__ out)
{
    extern __shared__ float sm[];
    float*  W2s = sm;                                // 4096
    float4* W1p = (float4*)(sm + DDIM*DDIM);         // 64 float4
    float*  b2s = sm + DDIM*DDIM + 4*DDIM;           // 64
    float*  stg = sm + DDIM*DDIM + 4*DDIM + DDIM;    // 128 x 64 staging

    int tid = threadIdx.x;
    for (int i = tid; i < DDIM*DDIM; i += 128) W2s[i] = W2[i];
    if (tid < DDIM) {
        W1p[tid] = make_float4(W1[tid], W1[DDIM + tid], W1[2*DDIM + tid], b1[tid]);
        b2s[tid] = b2[tid];
    }
    __syncthreads();

    int kh = blockIdx.x & 1;
    int nt = (blockIdx.x >> 1) & 255;
    int b  = blockIdx.x >> 9;
    int j  = tid & 15;                 // n within tile
    int qp = (tid >> 4) & 1;           // k-parity
    int eh = tid >> 5;                 // output-column quarter (warp-uniform)
    int n  = nt * 16 + j;

    const int* kr = g_knn + (((size_t)b * NPTS + n) << 4) + kh * 8 + qp;
    const float* xb = xyz + (size_t)b * NPTS * 3;
    float px = xb[3*n], py = xb[3*n+1], pz = xb[3*n+2];

    float dx[4], dy[4], dz[4];
#pragma unroll
    for (int u = 0; u < 4; u++) {
        int m = kr[2 * u];
        dx[u] = px - xb[3*m];
        dy[u] = py - xb[3*m+1];
        dz[u] = pz - xb[3*m+2];
    }

    ull acc[4][8];
    const ull* b2p = (const ull*)(b2s + (eh << 4));
#pragma unroll
    for (int u = 0; u < 4; u++)
#pragma unroll
        for (int e = 0; e < 8; e++) acc[u][e] = b2p[e];

#pragma unroll 4
    for (int d = 0; d < DDIM; d++) {
        float4 w1 = W1p[d];
        float h[4];
        unsigned z = 1;
#pragma unroll
        for (int u = 0; u < 4; u++) {
            h[u] = fmaf(dz[u], w1.z, fmaf(dy[u], w1.y, fmaf(dx[u], w1.x, w1.w)));
            h[u] = fmaxf(h[u], 0.0f);
            z &= (h[u] == 0.0f);
        }
        if (__all_sync(0xffffffffu, z)) continue;   // dead ReLU row skip
        ull h2[4];
#pragma unroll
        for (int u = 0; u < 4; u++)
            asm("mov.b64 %0, {%1, %1};" : "=l"(h2[u]) : "r"(__float_as_int(h[u])));
        const ulonglong2* w = (const ulonglong2*)(W2s + (d << 6) + (eh << 4));
#pragma unroll
        for (int e = 0; e < 4; e++) {
            ulonglong2 wv = w[e];   // broadcast LDS.128
#pragma unroll
            for (int u = 0; u < 4; u++) {
                asm("fma.rn.f32x2 %0, %1, %2, %0;" : "+l"(acc[u][2*e])   : "l"(h2[u]), "l"(wv.x));
                asm("fma.rn.f32x2 %0, %1, %2, %0;" : "+l"(acc[u][2*e+1]) : "l"(h2[u]), "l"(wv.y));
            }
        }
    }

    // Stage quarter-rows (XOR-swizzled float4 columns).
    ulonglong2* st2 = (ulonglong2*)stg;
#pragma unroll
    for (int u = 0; u < 4; u++) {
        int r = (qp + 2 * u) * 16 + j;      // staging row = k_local*16 + n
#pragma unroll
        for (int e = 0; e < 4; e++) {
            int c4 = (eh << 2) + e;
            ulonglong2 v; v.x = acc[u][2*e]; v.y = acc[u][2*e+1];
            st2[r * 16 + (c4 ^ (r & 15))] = v;
        }
    }
    __syncthreads();

    // Coalesced flush: out[b,k,n,:] = x[b,k,n,:] + pos_enc.
    const ulonglong2* xg = (const ulonglong2*)x;
    ulonglong2*       og = (ulonglong2*)out;
#pragma unroll
    for (int i = 0; i < 16; i++) {
        int f    = tid + 128 * i;
        int c4   = f & 15;
        int row  = f >> 4;
        int kk   = kh * 8 + (row >> 4);
        int jj   = row & 15;
        ulonglong2 pv = st2[row * 16 + (c4 ^ (row & 15))];
        size_t gi = ((((size_t)b * KNN + kk) * NPTS) + nt * 16 + jj) * 16 + c4;
        ulonglong2 xv = xg[gi];
        ulonglong2 r;
        asm("add.rn.f32x2 %0, %1, %2;" : "=l"(r.x) : "l"(pv.x), "l"(xv.x));
        asm("add.rn.f32x2 %0, %1, %2;" : "=l"(r.y) : "l"(pv.y), "l"(xv.y));
        og[gi] = r;
    }
}

extern "C" void kernel_launch(void* const* d_in, const int* in_sizes, int n_in,
                              void* d_out, int out_size) {
    const float* xyz = (const float*)d_in[0];
    const float* x   = (const float*)d_in[1];
    const float* W1  = (const float*)d_in[2];
    const float* b1  = (const float*)d_in[3];
    const float* W2  = (const float*)d_in[4];
    const float* b2  = (const float*)d_in[5];
    float* out = (float*)d_out;

    cudaFuncSetAttribute(knn_kernel, cudaFuncAttributeMaxDynamicSharedMemorySize,
                         KNN_SMEM);
    cudaFuncSetAttribute(mlp_kernel, cudaFuncAttributeMaxDynamicSharedMemorySize,
                         MLP_SMEM_FLOATS * (int)sizeof(float));

    knn_kernel<<<BDIM * NPTS / QPB, P1T, KNN_SMEM>>>(xyz);
    mlp_kernel<<<BDIM * 256 * 2, 128, MLP_SMEM_FLOATS * sizeof(float)>>>(
        xyz, x, W1, b1, W2, b2, out);
}